// round 1
// baseline (speedup 1.0000x reference)
#include <cuda_runtime.h>
#include <cstdint>

// ---------------------------------------------------------------------------
// Problem constants (fixed shapes per setup_inputs):
//   n1 = n2 = 4096, s = 192, a = 64, d = 256
// ---------------------------------------------------------------------------
#define N      4096
#define DIM    256
#define SDIM   192
#define ADIM   64
#define EPS    1e-8f

// ---------------------------------------------------------------------------
// Scratch (device globals — no allocations allowed)
// ---------------------------------------------------------------------------
__device__ float    g_sa [N * DIM];        // concat(state, action)      4 MB
__device__ float    g_esa[N * DIM];        // concat(expert_*)           4 MB
__device__ float    g_x2 [N];              // ||sa_i||^2
__device__ float    g_y2 [N];              // ||esa_j||^2
__device__ float    g_D  [(size_t)N * N];  // distance matrix           64 MB (reused)
__device__ float    g_D2 [DIM * DIM];      // 256x256 transposed-dist matrix
__device__ float    g_c2part[32 * DIM];    // partial column sumsq
__device__ float    g_c2 [DIM];            // column sumsq of esa
__device__ float    g_sim[N];              // similarity means (pass 1)
__device__ unsigned g_hist[256];           // radix-select histogram
__device__ unsigned g_prefix;              // radix-select prefix bits
__device__ unsigned g_k;                   // remaining rank
__device__ float    g_median[2];
__device__ float    g_gamma[2];

// ---------------------------------------------------------------------------
// 1) concat + per-row squared-norm. One block per row, 256 threads (== DIM).
// ---------------------------------------------------------------------------
__global__ void concat_norm_kernel(const float* __restrict__ st,
                                   const float* __restrict__ ac,
                                   float* __restrict__ cat,
                                   float* __restrict__ nrm) {
    int row = blockIdx.x;
    int t   = threadIdx.x;
    float v = (t < SDIM) ? st[row * SDIM + t] : ac[row * ADIM + (t - SDIM)];
    cat[row * DIM + t] = v;

    __shared__ float sh[256];
    sh[t] = v * v;
    __syncthreads();
    #pragma unroll
    for (int s = 128; s > 0; s >>= 1) {
        if (t < s) sh[t] += sh[t + s];
        __syncthreads();
    }
    if (t == 0) nrm[row] = sh[0];
}

// ---------------------------------------------------------------------------
// 2) Distance GEMM:  D[i,j] = (x2[i] + y2[j] - 2 * dot(A_i, B_j)) / 256
//    A,B row-major [N, 256].  64x64 tile, BK=32, 256 threads, 4x4/thread.
// ---------------------------------------------------------------------------
__global__ __launch_bounds__(256)
void dist_gemm_kernel(const float* __restrict__ A, const float* __restrict__ B,
                      const float* __restrict__ x2, const float* __restrict__ y2,
                      float* __restrict__ D) {
    __shared__ float As[32][65];   // [k][m], padded
    __shared__ float Bs[32][65];   // [k][n], padded

    const int tx = threadIdx.x & 15;
    const int ty = threadIdx.x >> 4;
    const int i0 = blockIdx.y * 64;
    const int j0 = blockIdx.x * 64;

    float acc[4][4] = {};

    for (int k0 = 0; k0 < DIM; k0 += 32) {
        #pragma unroll
        for (int r = 0; r < 8; r++) {
            int idx = threadIdx.x + r * 256;
            int row = idx >> 5;       // 0..63
            int col = idx & 31;       // 0..31
            As[col][row] = A[(size_t)(i0 + row) * DIM + k0 + col];
            Bs[col][row] = B[(size_t)(j0 + row) * DIM + k0 + col];
        }
        __syncthreads();
        #pragma unroll
        for (int kk = 0; kk < 32; kk++) {
            float a[4], b[4];
            #pragma unroll
            for (int q = 0; q < 4; q++) {
                a[q] = As[kk][ty + 16 * q];
                b[q] = Bs[kk][tx + 16 * q];
            }
            #pragma unroll
            for (int p = 0; p < 4; p++)
                #pragma unroll
                for (int q = 0; q < 4; q++)
                    acc[p][q] += a[p] * b[q];
        }
        __syncthreads();
    }

    #pragma unroll
    for (int p = 0; p < 4; p++) {
        int i = i0 + ty + 16 * p;
        float xi = x2[i];
        #pragma unroll
        for (int q = 0; q < 4; q++) {
            int j = j0 + tx + 16 * q;
            D[(size_t)i * N + j] = (xi + y2[j] - 2.0f * acc[p][q]) * (1.0f / 256.0f);
        }
    }
}

// ---------------------------------------------------------------------------
// 3) Column sumsq of esa (c2[j] = sum_i esa[i][j]^2). Deterministic partials.
// ---------------------------------------------------------------------------
__global__ void colnorm_part_kernel() {
    int b = blockIdx.x;            // 32 blocks, 128 rows each
    int t = threadIdx.x;           // 256 threads == columns
    float s = 0.f;
    int r0 = b * 128;
    for (int r = 0; r < 128; r++) {
        float v = g_esa[(size_t)(r0 + r) * DIM + t];
        s += v * v;
    }
    g_c2part[b * DIM + t] = s;
}
__global__ void colnorm_reduce_kernel() {
    int t = threadIdx.x;
    float s = 0.f;
    for (int b = 0; b < 32; b++) s += g_c2part[b * DIM + t];
    g_c2[t] = s;
}

// ---------------------------------------------------------------------------
// 4) D2[i,j] = (c2[i] + c2[j] - 2 * sum_k esa[k][i]*esa[k][j]) / 4096
//    Grid (16,16), 256 threads = 16x16, one output each, K-chunks of 64.
// ---------------------------------------------------------------------------
__global__ __launch_bounds__(256)
void d2_kernel() {
    __shared__ float Ei[64][16];
    __shared__ float Ej[64][16];
    const int tx = threadIdx.x & 15;
    const int ty = threadIdx.x >> 4;
    const int i0 = blockIdx.y * 16;
    const int j0 = blockIdx.x * 16;

    float acc = 0.f;
    for (int k0 = 0; k0 < N; k0 += 64) {
        #pragma unroll
        for (int r = 0; r < 4; r++) {
            int idx = threadIdx.x + r * 256;
            int kk = idx >> 4, ii = idx & 15;
            Ei[kk][ii] = g_esa[(size_t)(k0 + kk) * DIM + i0 + ii];
            Ej[kk][ii] = g_esa[(size_t)(k0 + kk) * DIM + j0 + ii];
        }
        __syncthreads();
        #pragma unroll
        for (int kk = 0; kk < 64; kk++)
            acc += Ei[kk][ty] * Ej[kk][tx];
        __syncthreads();
    }
    int i = i0 + ty, j = j0 + tx;
    g_D2[i * DIM + j] = (g_c2[i] + g_c2[j] - 2.0f * acc) * (1.0f / 4096.0f);
}

// ---------------------------------------------------------------------------
// 5) Exact lower-median via MSB-first radix select (4 x 8-bit passes),
//    fully device-side so the whole thing is graph-capturable.
//    Float -> monotone uint mapping handles possible tiny negatives.
// ---------------------------------------------------------------------------
__device__ __forceinline__ unsigned f2u_mono(float f) {
    unsigned b = __float_as_uint(f);
    return (b & 0x80000000u) ? ~b : (b | 0x80000000u);
}

__global__ void select_init_kernel(unsigned k) {
    if (threadIdx.x == 0) { g_prefix = 0u; g_k = k; }
    g_hist[threadIdx.x] = 0u;   // 256 threads
}

__global__ void select_hist_kernel(const float* __restrict__ data, unsigned n, int shift) {
    __shared__ unsigned sh[256];
    sh[threadIdx.x] = 0u;
    __syncthreads();
    unsigned prefix = g_prefix;
    unsigned stride = gridDim.x * blockDim.x;
    for (unsigned i = blockIdx.x * blockDim.x + threadIdx.x; i < n; i += stride) {
        unsigned u = f2u_mono(data[i]);
        bool ok = (shift == 24) || ((u >> (shift + 8)) == prefix);
        if (ok) atomicAdd(&sh[(u >> shift) & 0xFFu], 1u);
    }
    __syncthreads();
    if (sh[threadIdx.x]) atomicAdd(&g_hist[threadIdx.x], sh[threadIdx.x]);
}

__global__ void select_scan_kernel() {
    // single thread: pick bucket, update prefix/rank, clear hist for next pass
    unsigned k = g_k, run = 0; unsigned bucket = 0;
    for (int b = 0; b < 256; b++) {
        unsigned c = g_hist[b];
        if (k < run + c) { bucket = (unsigned)b; break; }
        run += c;
    }
    g_k = k - run;
    g_prefix = (g_prefix << 8) | bucket;
    for (int b = 0; b < 256; b++) g_hist[b] = 0u;
}

__global__ void select_finalize_kernel(int idx) {
    unsigned u = g_prefix;
    unsigned bits = (u & 0x80000000u) ? (u ^ 0x80000000u) : ~u;
    g_median[idx] = __uint_as_float(bits);
}

__global__ void gamma_kernel() {
    g_gamma[0] = 1.0f / (g_median[0] + EPS);
    g_gamma[1] = 1.0f / (g_median[1] + EPS);
}

// ---------------------------------------------------------------------------
// 6) Row means of exp(-g1*D) + exp(-g2*D).
//    Pass 1 (out==nullptr): g_sim[i] = mean.  Pass 2: out[i] = g_sim[i] - mean.
// ---------------------------------------------------------------------------
__global__ __launch_bounds__(256)
void rowsum_kernel(const float* __restrict__ D, float* __restrict__ out) {
    int i = blockIdx.x;
    int t = threadIdx.x;
    float g1 = g_gamma[0], g2 = g_gamma[1];
    const float* row = D + (size_t)i * N;
    float s = 0.f;
    for (int j = t; j < N; j += 256) {
        float d = row[j];
        s += expf(-g1 * d) + expf(-g2 * d);
    }
    __shared__ float sh[256];
    sh[t] = s;
    __syncthreads();
    #pragma unroll
    for (int k = 128; k > 0; k >>= 1) {
        if (t < k) sh[t] += sh[t + k];
        __syncthreads();
    }
    if (t == 0) {
        float m = sh[0] * (1.0f / (float)N);
        if (out) out[i] = g_sim[i] - m;
        else     g_sim[i] = m;
    }
}

// ---------------------------------------------------------------------------
// Host orchestration — pure kernel launches on the default stream.
// ---------------------------------------------------------------------------
static void run_select(const float* data, unsigned n, unsigned k, int idx) {
    unsigned blocks = (n + 255u) / 256u;
    if (blocks > 2048u) blocks = 2048u;
    select_init_kernel<<<1, 256>>>(k);
    const int shifts[4] = {24, 16, 8, 0};
    for (int p = 0; p < 4; p++) {
        select_hist_kernel<<<blocks, 256>>>(data, n, shifts[p]);
        select_scan_kernel<<<1, 1>>>();
    }
    select_finalize_kernel<<<1, 1>>>(idx);
}

extern "C" void kernel_launch(void* const* d_in, const int* in_sizes, int n_in,
                              void* d_out, int out_size) {
    const float* state   = (const float*)d_in[0];
    const float* action  = (const float*)d_in[1];
    const float* estate  = (const float*)d_in[2];
    const float* eaction = (const float*)d_in[3];
    float* out = (float*)d_out;

    float *p_sa, *p_esa, *p_x2, *p_y2, *p_D, *p_D2;
    cudaGetSymbolAddress((void**)&p_sa,  g_sa);
    cudaGetSymbolAddress((void**)&p_esa, g_esa);
    cudaGetSymbolAddress((void**)&p_x2,  g_x2);
    cudaGetSymbolAddress((void**)&p_y2,  g_y2);
    cudaGetSymbolAddress((void**)&p_D,   g_D);
    cudaGetSymbolAddress((void**)&p_D2,  g_D2);

    // 1) concat + norms
    concat_norm_kernel<<<N, 256>>>(state,  action,  p_sa,  p_x2);
    concat_norm_kernel<<<N, 256>>>(estate, eaction, p_esa, p_y2);

    // 2) D_agent_expert -> g_D
    dim3 ggrid(N / 64, N / 64);
    dist_gemm_kernel<<<ggrid, 256>>>(p_sa, p_esa, p_x2, p_y2, p_D);

    // 3) small transposed-distance matrix (for gamma_2)
    colnorm_part_kernel<<<32, 256>>>();
    colnorm_reduce_kernel<<<1, 256>>>();
    d2_kernel<<<dim3(16, 16), 256>>>();

    // 4) exact lower medians -> gammas
    //    lower median index = (count-1)//2, 0-indexed k-th smallest
    run_select(p_D,  (unsigned)N * (unsigned)N, ((unsigned)N * (unsigned)N - 1u) / 2u, 0);
    run_select(p_D2, (unsigned)(DIM * DIM),     ((unsigned)(DIM * DIM) - 1u) / 2u,     1);
    gamma_kernel<<<1, 1>>>();

    // 5) similarity means from stored D_agent_expert
    //    (mean over expert axis == mean over j of row i, by symmetry of the
    //     transpose in the reference)
    rowsum_kernel<<<N, 256>>>(p_D, nullptr);

    // 6) D_self reuses g_D, then final output = sim - self_sim
    dist_gemm_kernel<<<ggrid, 256>>>(p_sa, p_sa, p_x2, p_x2, p_D);
    rowsum_kernel<<<N, 256>>>(p_D, out);
}

// round 3
// speedup vs baseline: 1.9536x; 1.9536x over previous
#include <cuda_runtime.h>
#include <cuda_bf16.h>
#include <cstdint>

// ---------------------------------------------------------------------------
// Shapes: n1 = n2 = 4096, s = 192, a = 64, d = 256. Split-GEMM K = 768.
// ---------------------------------------------------------------------------
#define N      4096
#define DIM    256
#define SDIM   192
#define ADIM   64
#define KSPLIT 768
#define EPS    1e-8f

// ---------------------------------------------------------------------------
// Scratch (device globals — allocations forbidden)
// ---------------------------------------------------------------------------
__device__ __align__(256) float g_sa [N * DIM];
__device__ __align__(256) float g_esa[N * DIM];
__device__ __align__(256) float g_x2 [N];
__device__ __align__(256) float g_y2 [N];
__device__ __align__(256) float g_D  [(size_t)N * N];       // 64 MB, reused
__device__ __align__(256) float g_D2 [DIM * DIM];
__device__ __align__(256) float g_D2p[8 * DIM * DIM];
__device__ __align__(256) float g_c2part[32 * DIM];
__device__ __align__(256) float g_c2 [DIM];
__device__ __align__(256) float g_sim[N];
__device__ __align__(256) __nv_bfloat16 g_P[(size_t)N * KSPLIT]; // sa  [hi|hi|lo]
__device__ __align__(256) __nv_bfloat16 g_Q[(size_t)N * KSPLIT]; // sa  [hi|lo|hi]
__device__ __align__(256) __nv_bfloat16 g_R[(size_t)N * KSPLIT]; // esa [hi|lo|hi]
__device__ unsigned g_hist[256];
__device__ unsigned g_prefix;
__device__ unsigned g_k;
__device__ float    g_median[2];
__device__ float    g_gamma[2];

// ---------------------------------------------------------------------------
// helpers
// ---------------------------------------------------------------------------
__device__ __forceinline__ uint32_t smem_u32(const void* p) {
    uint32_t a;
    asm("{ .reg .u64 t; cvta.to.shared.u64 t, %1; cvt.u32.u64 %0, t; }"
        : "=r"(a) : "l"(p));
    return a;
}
#define SW128B(o) ((o) ^ (((o) >> 3) & 0x70))

__device__ __forceinline__ void cp_async16(uint32_t sdst, const void* gsrc) {
    asm volatile("cp.async.cg.shared.global [%0], [%1], 16;"
                 :: "r"(sdst), "l"(gsrc) : "memory");
}
__device__ __forceinline__ void cp_commit() {
    asm volatile("cp.async.commit_group;" ::: "memory");
}
__device__ __forceinline__ void ldmx4(uint32_t& r0, uint32_t& r1,
                                      uint32_t& r2, uint32_t& r3, uint32_t addr) {
    asm volatile("ldmatrix.sync.aligned.m8n8.x4.shared.b16 {%0,%1,%2,%3}, [%4];"
                 : "=r"(r0), "=r"(r1), "=r"(r2), "=r"(r3) : "r"(addr));
}
__device__ __forceinline__ void mma_bf16(float& c0, float& c1, float& c2, float& c3,
                                         uint32_t a0, uint32_t a1, uint32_t a2, uint32_t a3,
                                         uint32_t b0, uint32_t b1) {
    asm volatile(
        "mma.sync.aligned.m16n8k16.row.col.f32.bf16.bf16.f32 "
        "{%0,%1,%2,%3}, {%4,%5,%6,%7}, {%8,%9}, {%0,%1,%2,%3};"
        : "+f"(c0), "+f"(c1), "+f"(c2), "+f"(c3)
        : "r"(a0), "r"(a1), "r"(a2), "r"(a3), "r"(b0), "r"(b1));
}

// ---------------------------------------------------------------------------
// 1) concat + per-row squared-norm (exact fp32)
// ---------------------------------------------------------------------------
__global__ void concat_norm_kernel(const float* __restrict__ st,
                                   const float* __restrict__ ac,
                                   float* __restrict__ cat,
                                   float* __restrict__ nrm) {
    int row = blockIdx.x, t = threadIdx.x;
    float v = (t < SDIM) ? st[row * SDIM + t] : ac[row * ADIM + (t - SDIM)];
    cat[row * DIM + t] = v;
    __shared__ float sh[256];
    sh[t] = v * v;
    __syncthreads();
    #pragma unroll
    for (int s = 128; s > 0; s >>= 1) {
        if (t < s) sh[t] += sh[t + s];
        __syncthreads();
    }
    if (t == 0) nrm[row] = sh[0];
}

// ---------------------------------------------------------------------------
// 2) bf16 hi/lo split, K-concatenated: phl=1 -> [hi|hi|lo], 0 -> [hi|lo|hi]
// ---------------------------------------------------------------------------
__global__ void split_kernel(const float* __restrict__ src,
                             __nv_bfloat16* __restrict__ dst, int phl) {
    int row = blockIdx.x, t = threadIdx.x;
    float x = src[row * DIM + t];
    __nv_bfloat16 hi = __float2bfloat16(x);
    __nv_bfloat16 lo = __float2bfloat16(x - __bfloat162float(hi));
    size_t base = (size_t)row * KSPLIT + t;
    dst[base]       = hi;
    dst[base + 256] = phl ? hi : lo;
    dst[base + 512] = phl ? lo : hi;
}

// ---------------------------------------------------------------------------
// 3) HMMA distance GEMM: 128x128 CTA tile, 8 warps of 64x32,
//    mma.sync.m16n8k16 bf16, SW128 smem + ldmatrix, cp.async double buffer.
//    D[i,j] = (x2[i] + y2[j] - 2*dot(A_i,B_j)) / 256,  K = 768 (12 chunks)
// ---------------------------------------------------------------------------
#define BK        64
#define TILE_B    (128 * BK * 2)          // 16 KB per operand per stage
#define GM_SMEM   (4 * TILE_B)            // 64 KB (2 stages x (A+B))
#define NCHUNK    12

__device__ __forceinline__ void gemm_issue_stage(
    const __nv_bfloat16* __restrict__ A, const __nv_bfloat16* __restrict__ B,
    int i0, int j0, int c, uint32_t sA, uint32_t sB, int tid)
{
    const __nv_bfloat16* Ap = A + (size_t)i0 * KSPLIT + c * BK;
    const __nv_bfloat16* Bp = B + (size_t)j0 * KSPLIT + c * BK;
    #pragma unroll
    for (int q = 0; q < 4; q++) {         // 128 rows x 8 chunks of 16B
        int idx = tid + q * 256;
        int row = idx >> 3, seg = idx & 7;
        cp_async16(sA + SW128B(row * 128 + seg * 16),
                   Ap + (size_t)row * KSPLIT + seg * 8);
    }
    #pragma unroll
    for (int q = 0; q < 4; q++) {
        int idx = tid + q * 256;
        int row = idx >> 3, seg = idx & 7;
        cp_async16(sB + SW128B(row * 128 + seg * 16),
                   Bp + (size_t)row * KSPLIT + seg * 8);
    }
    cp_commit();
}

__global__ __launch_bounds__(256, 1)
void hmma_dist_gemm(const __nv_bfloat16* __restrict__ A,
                    const __nv_bfloat16* __restrict__ B,
                    const float* __restrict__ x2,
                    const float* __restrict__ y2,
                    float* __restrict__ D)
{
    extern __shared__ char smem[];
    const uint32_t sb = smem_u32(smem);
    const int tid = threadIdx.x;
    const int wid = tid >> 5, lane = tid & 31;
    const int warp_m = wid >> 2, warp_n = wid & 3;   // 2 x 4 warps
    const int i0 = blockIdx.y * 128;
    const int j0 = blockIdx.x * 128;

    // stage s: A at sb + s*32KB, B at +16KB
    uint32_t sA[2] = { sb,              sb + 2 * TILE_B };
    uint32_t sB[2] = { sb + TILE_B,     sb + 3 * TILE_B };

    float acc[4][4][4];
    #pragma unroll
    for (int mi = 0; mi < 4; mi++)
        #pragma unroll
        for (int ni = 0; ni < 4; ni++)
            #pragma unroll
            for (int e = 0; e < 4; e++) acc[mi][ni][e] = 0.f;

    gemm_issue_stage(A, B, i0, j0, 0, sA[0], sB[0], tid);
    gemm_issue_stage(A, B, i0, j0, 1, sA[1], sB[1], tid);

    // precomputed ldmatrix lane offsets
    const int a_row = (lane & 15);
    const int a_col = (lane & 16) ? 8 : 0;
    const int b_row = (lane & 7) + ((lane & 16) >> 1);
    const int b_col = (lane & 8) ? 8 : 0;

    for (int c = 0; c < NCHUNK; c++) {
        if (c < NCHUNK - 2) asm volatile("cp.async.wait_group 1;" ::: "memory");
        else                asm volatile("cp.async.wait_group 0;" ::: "memory");
        __syncthreads();

        uint32_t cA = sA[c & 1], cB = sB[c & 1];
        #pragma unroll
        for (int ks = 0; ks < BK / 16; ks++) {
            int k0 = ks * 16;
            uint32_t a[4][4], b[2][4];
            #pragma unroll
            for (int mi = 0; mi < 4; mi++) {
                int row = warp_m * 64 + mi * 16 + a_row;
                ldmx4(a[mi][0], a[mi][1], a[mi][2], a[mi][3],
                      cA + SW128B(row * 128 + (k0 + a_col) * 2));
            }
            #pragma unroll
            for (int nb = 0; nb < 2; nb++) {
                int row = warp_n * 32 + nb * 16 + b_row;
                ldmx4(b[nb][0], b[nb][1], b[nb][2], b[nb][3],
                      cB + SW128B(row * 128 + (k0 + b_col) * 2));
            }
            #pragma unroll
            for (int mi = 0; mi < 4; mi++)
                #pragma unroll
                for (int ni = 0; ni < 4; ni++)
                    mma_bf16(acc[mi][ni][0], acc[mi][ni][1],
                             acc[mi][ni][2], acc[mi][ni][3],
                             a[mi][0], a[mi][1], a[mi][2], a[mi][3],
                             b[ni >> 1][(ni & 1) * 2], b[ni >> 1][(ni & 1) * 2 + 1]);
        }
        __syncthreads();
        if (c + 2 < NCHUNK)
            gemm_issue_stage(A, B, i0, j0, c + 2, sA[c & 1], sB[c & 1], tid);
    }

    // epilogue: fused distance, float2 stores
    const int qrow = lane >> 2;            // 0..7
    const int qcol = (lane & 3) * 2;       // 0,2,4,6
    #pragma unroll
    for (int mi = 0; mi < 4; mi++) {
        int i_lo = i0 + warp_m * 64 + mi * 16 + qrow;
        int i_hi = i_lo + 8;
        float xlo = x2[i_lo], xhi = x2[i_hi];
        #pragma unroll
        for (int ni = 0; ni < 4; ni++) {
            int j = j0 + warp_n * 32 + ni * 8 + qcol;
            float yj0 = y2[j], yj1 = y2[j + 1];
            float2 vlo, vhi;
            vlo.x = (xlo + yj0 - 2.f * acc[mi][ni][0]) * 0.00390625f;
            vlo.y = (xlo + yj1 - 2.f * acc[mi][ni][1]) * 0.00390625f;
            vhi.x = (xhi + yj0 - 2.f * acc[mi][ni][2]) * 0.00390625f;
            vhi.y = (xhi + yj1 - 2.f * acc[mi][ni][3]) * 0.00390625f;
            *(float2*)(D + (size_t)i_lo * N + j) = vlo;
            *(float2*)(D + (size_t)i_hi * N + j) = vhi;
        }
    }
}

// ---------------------------------------------------------------------------
// 4) gamma_2 path: column sumsq + K-split Gram of esa columns
// ---------------------------------------------------------------------------
__global__ void colnorm_part_kernel() {
    int b = blockIdx.x, t = threadIdx.x;
    float s = 0.f;
    int r0 = b * 128;
    for (int r = 0; r < 128; r++) {
        float v = g_esa[(size_t)(r0 + r) * DIM + t];
        s += v * v;
    }
    g_c2part[b * DIM + t] = s;
}
__global__ void colnorm_reduce_kernel() {
    int t = threadIdx.x;
    float s = 0.f;
    for (int b = 0; b < 32; b++) s += g_c2part[b * DIM + t];
    g_c2[t] = s;
}
__global__ __launch_bounds__(256)
void d2_part_kernel() {
    __shared__ float Ei[64][32];
    __shared__ float Ej[64][32];
    const int tx = threadIdx.x & 15, ty = threadIdx.x >> 4;
    const int i0 = blockIdx.y * 32, j0 = blockIdx.x * 32;
    const int k0 = blockIdx.z * 512;
    float a00 = 0, a01 = 0, a10 = 0, a11 = 0;
    for (int kc = k0; kc < k0 + 512; kc += 64) {
        #pragma unroll
        for (int r = 0; r < 8; r++) {
            int idx = threadIdx.x + r * 256;
            int kk = idx >> 5, col = idx & 31;
            Ei[kk][col] = g_esa[(size_t)(kc + kk) * DIM + i0 + col];
            Ej[kk][col] = g_esa[(size_t)(kc + kk) * DIM + j0 + col];
        }
        __syncthreads();
        #pragma unroll
        for (int kk = 0; kk < 64; kk++) {
            float xa = Ei[kk][ty], xb = Ei[kk][ty + 16];
            float ya = Ej[kk][tx], yb = Ej[kk][tx + 16];
            a00 += xa * ya; a01 += xa * yb; a10 += xb * ya; a11 += xb * yb;
        }
        __syncthreads();
    }
    float* P = g_D2p + (size_t)blockIdx.z * DIM * DIM;
    P[(i0 + ty) * DIM + j0 + tx]           = a00;
    P[(i0 + ty) * DIM + j0 + tx + 16]      = a01;
    P[(i0 + ty + 16) * DIM + j0 + tx]      = a10;
    P[(i0 + ty + 16) * DIM + j0 + tx + 16] = a11;
}
__global__ void d2_final_kernel() {
    int i = blockIdx.x, j = threadIdx.x;
    float s = 0.f;
    #pragma unroll
    for (int z = 0; z < 8; z++) s += g_D2p[(size_t)z * DIM * DIM + i * DIM + j];
    g_D2[i * DIM + j] = (g_c2[i] + g_c2[j] - 2.f * s) * (1.f / 4096.f);
}

// ---------------------------------------------------------------------------
// 5) Exact lower-median: MSB radix select, warp-aggregated histogram
// ---------------------------------------------------------------------------
__device__ __forceinline__ unsigned f2u_mono(float f) {
    unsigned b = __float_as_uint(f);
    return (b & 0x80000000u) ? ~b : (b | 0x80000000u);
}
__global__ void select_init_kernel(unsigned k) {
    if (threadIdx.x == 0) { g_prefix = 0u; g_k = k; }
    g_hist[threadIdx.x] = 0u;
}
__global__ void select_hist_kernel(const float* __restrict__ data, unsigned n4, int shift) {
    __shared__ unsigned sh[256];
    sh[threadIdx.x] = 0u;
    __syncthreads();
    unsigned prefix = g_prefix;
    unsigned stride = gridDim.x * blockDim.x;
    int lane = threadIdx.x & 31;
    const float4* d4 = (const float4*)data;
    for (unsigned base = blockIdx.x * blockDim.x; base < n4; base += stride) {
        unsigned i = base + threadIdx.x;
        float4 v = make_float4(0.f, 0.f, 0.f, 0.f);
        bool valid = (i < n4);
        if (valid) v = d4[i];
        float vals[4] = {v.x, v.y, v.z, v.w};
        #pragma unroll
        for (int e = 0; e < 4; e++) {
            unsigned bucket = 0xFFFFFFFFu;
            if (valid) {
                unsigned u = f2u_mono(vals[e]);
                bool ok = (shift == 24) || ((u >> (shift + 8)) == prefix);
                if (ok) bucket = (u >> shift) & 0xFFu;
            }
            unsigned m = __match_any_sync(0xFFFFFFFFu, bucket);
            if (bucket != 0xFFFFFFFFu && lane == __ffs(m) - 1)
                atomicAdd(&sh[bucket], (unsigned)__popc(m));
        }
    }
    __syncthreads();
    if (sh[threadIdx.x]) atomicAdd(&g_hist[threadIdx.x], sh[threadIdx.x]);
}
__global__ void select_scan_kernel() {
    __shared__ unsigned s[256];
    int t = threadIdx.x;
    unsigned c = g_hist[t];
    s[t] = c;
    __syncthreads();
    for (int off = 1; off < 256; off <<= 1) {
        unsigned v = (t >= off) ? s[t - off] : 0u;
        __syncthreads();
        s[t] += v;
        __syncthreads();
    }
    unsigned k = g_k;
    unsigned incl = s[t], excl = incl - c;
    if (k >= excl && k < incl) {
        g_k = k - excl;
        g_prefix = (g_prefix << 8) | (unsigned)t;
    }
    g_hist[t] = 0u;
}
__global__ void select_finalize_kernel(int idx) {
    unsigned u = g_prefix;
    unsigned bits = (u & 0x80000000u) ? (u ^ 0x80000000u) : ~u;
    g_median[idx] = __uint_as_float(bits);
}
__global__ void gamma_kernel() {
    g_gamma[0] = 1.0f / (g_median[0] + EPS);
    g_gamma[1] = 1.0f / (g_median[1] + EPS);
}

// ---------------------------------------------------------------------------
// 6) Row means of exp(-g1*D) + exp(-g2*D)
// ---------------------------------------------------------------------------
__global__ __launch_bounds__(256)
void rowsum_kernel(const float* __restrict__ D, float* __restrict__ out) {
    int i = blockIdx.x, t = threadIdx.x;
    float g1 = g_gamma[0], g2 = g_gamma[1];
    const float4* row = (const float4*)(D + (size_t)i * N);
    float s = 0.f;
    #pragma unroll 4
    for (int j = t; j < N / 4; j += 256) {
        float4 v = row[j];
        s += __expf(-g1 * v.x) + __expf(-g1 * v.y) + __expf(-g1 * v.z) + __expf(-g1 * v.w)
           + __expf(-g2 * v.x) + __expf(-g2 * v.y) + __expf(-g2 * v.z) + __expf(-g2 * v.w);
    }
    __shared__ float sh[256];
    sh[t] = s;
    __syncthreads();
    #pragma unroll
    for (int k = 128; k > 0; k >>= 1) {
        if (t < k) sh[t] += sh[t + k];
        __syncthreads();
    }
    if (t == 0) {
        float m = sh[0] * (1.0f / (float)N);
        if (out) out[i] = g_sim[i] - m;
        else     g_sim[i] = m;
    }
}

// ---------------------------------------------------------------------------
// Host orchestration (graph-capturable: kernel launches only)
// ---------------------------------------------------------------------------
static void run_select(const float* data, unsigned n, unsigned k, int idx) {
    unsigned n4 = n / 4;
    unsigned blocks = (n4 + 255u) / 256u;
    if (blocks > 2048u) blocks = 2048u;
    select_init_kernel<<<1, 256>>>(k);
    const int shifts[4] = {24, 16, 8, 0};
    for (int p = 0; p < 4; p++) {
        select_hist_kernel<<<blocks, 256>>>(data, n4, shifts[p]);
        select_scan_kernel<<<1, 256>>>();
    }
    select_finalize_kernel<<<1, 1>>>(idx);
}

extern "C" void kernel_launch(void* const* d_in, const int* in_sizes, int n_in,
                              void* d_out, int out_size) {
    const float* state   = (const float*)d_in[0];
    const float* action  = (const float*)d_in[1];
    const float* estate  = (const float*)d_in[2];
    const float* eaction = (const float*)d_in[3];
    float* out = (float*)d_out;

    float *p_sa, *p_esa, *p_x2, *p_y2, *p_D, *p_D2;
    __nv_bfloat16 *p_P, *p_Q, *p_R;
    cudaGetSymbolAddress((void**)&p_sa,  g_sa);
    cudaGetSymbolAddress((void**)&p_esa, g_esa);
    cudaGetSymbolAddress((void**)&p_x2,  g_x2);
    cudaGetSymbolAddress((void**)&p_y2,  g_y2);
    cudaGetSymbolAddress((void**)&p_D,   g_D);
    cudaGetSymbolAddress((void**)&p_D2,  g_D2);
    cudaGetSymbolAddress((void**)&p_P,   g_P);
    cudaGetSymbolAddress((void**)&p_Q,   g_Q);
    cudaGetSymbolAddress((void**)&p_R,   g_R);

    cudaFuncSetAttribute(hmma_dist_gemm,
                         cudaFuncAttributeMaxDynamicSharedMemorySize, GM_SMEM);

    // 1) concat + exact norms
    concat_norm_kernel<<<N, 256>>>(state,  action,  p_sa,  p_x2);
    concat_norm_kernel<<<N, 256>>>(estate, eaction, p_esa, p_y2);

    // 2) bf16 hi/lo K-concat splits
    split_kernel<<<N, 256>>>(p_sa,  p_P, 1);   // [hi|hi|lo]
    split_kernel<<<N, 256>>>(p_sa,  p_Q, 0);   // [hi|lo|hi]
    split_kernel<<<N, 256>>>(p_esa, p_R, 0);   // [hi|lo|hi]

    // 3) D_agent_expert via HMMA
    dim3 ggrid(N / 128, N / 128);
    hmma_dist_gemm<<<ggrid, 256, GM_SMEM>>>(p_P, p_R, p_x2, p_y2, p_D);

    // 4) gamma_2 small distance matrix
    colnorm_part_kernel<<<32, 256>>>();
    colnorm_reduce_kernel<<<1, 256>>>();
    d2_part_kernel<<<dim3(8, 8, 8), 256>>>();
    d2_final_kernel<<<DIM, DIM>>>();

    // 5) exact lower medians -> gammas
    run_select(p_D,  (unsigned)N * (unsigned)N, ((unsigned)N * (unsigned)N - 1u) / 2u, 0);
    run_select(p_D2, (unsigned)(DIM * DIM),     ((unsigned)(DIM * DIM) - 1u) / 2u,     1);
    gamma_kernel<<<1, 1>>>();

    // 6) similarity means from D_agent_expert
    rowsum_kernel<<<N, 256>>>(p_D, nullptr);

    // 7) D_self (reuses g_D)
    hmma_dist_gemm<<<ggrid, 256, GM_SMEM>>>(p_P, p_Q, p_x2, p_x2, p_D);
    rowsum_kernel<<<N, 256>>>(p_D, out);
}